// round 13
// baseline (speedup 1.0000x reference)
#include <cuda_runtime.h>
#include <cuda_bf16.h>
#include <math.h>
#include <stdint.h>

#define N_NODES  50000
#define N_EDGES  600000
#define D_IN     1024
#define D_H      128
#define N_GRAPHS 1000
#define MPAD     50048            // 391 * 128

// ================= device scratch (static, no allocation) =================
__device__ int   g_is64;
__device__ int   g_cnt[N_NODES];
__device__ int   g_rowptr[N_NODES + 1];
__device__ int   g_wptr[N_NODES];
__device__ int   g_csrc[N_EDGES];
__device__ int   g_blk[128];
__device__ int   g_blkoff[128];

__device__ float g_q   [(size_t)N_NODES * D_H];
__device__ float g_kv  [(size_t)N_NODES * 2 * D_H];   // k at [0,128), v at [128,256)
__device__ float g_skip[(size_t)N_NODES * D_H];
__device__ float g_h0  [(size_t)N_NODES * D_H];
__device__ float g_h1  [(size_t)N_NODES * D_H];

// bf16 A images (padded to MPAD rows)
__device__ __align__(16) __nv_bfloat16 g_xbf [(size_t)MPAD * D_IN];   // 102.5 MB
__device__ __align__(16) __nv_bfloat16 g_h0bf[(size_t)MPAD * D_H];    // 12.8 MB

// pre-packed bf16 weight tiles: [chunk64][w][128 n][64 k]
__device__ __align__(16) __nv_bfloat16 g_bpre0[16 * 4 * 8192];  // 1 MB
__device__ __align__(16) __nv_bfloat16 g_bpre1[2  * 4 * 8192];  // 128 KB
__device__ float g_bias0[512];
__device__ float g_bias1[512];

// ================= index dtype detection (int64 vs int32) =================
__global__ void detect_idx_dtype(const long long* __restrict__ p) {
    __shared__ int bad;
    if (threadIdx.x == 0) bad = 0;
    __syncthreads();
    long long v = p[threadIdx.x];
    if (v < 0 || v >= N_NODES) atomicOr(&bad, 1);
    __syncthreads();
    if (threadIdx.x == 0) g_is64 = (bad == 0) ? 1 : 0;
}
__device__ __forceinline__ int edge_at(const void* ei, int pos) {
    if (g_is64) return (int)((const long long*)ei)[pos];
    return ((const int*)ei)[pos];
}

// ================= CSR build =================
__global__ void zero_cnt_kernel() {
    int i = blockIdx.x * blockDim.x + threadIdx.x;
    if (i < N_NODES) g_cnt[i] = 0;
}
__global__ void count_deg_kernel(const void* __restrict__ ei) {
    int e = blockIdx.x * blockDim.x + threadIdx.x;
    if (e < N_EDGES) atomicAdd(&g_cnt[edge_at(ei, N_EDGES + e)], 1);
}
__global__ void scan1_kernel() {
    __shared__ int ws[16];
    const int t = threadIdx.x, lane = t & 31, w = t >> 5;
    const int i = blockIdx.x * 512 + t;
    int v = (i < N_NODES) ? g_cnt[i] : 0;
    int x = v;
    #pragma unroll
    for (int off = 1; off < 32; off <<= 1) {
        int y = __shfl_up_sync(0xffffffffu, x, off);
        if (lane >= off) x += y;
    }
    if (lane == 31) ws[w] = x;
    __syncthreads();
    if (t < 16) {
        int s = ws[t];
        #pragma unroll
        for (int off = 1; off < 16; off <<= 1) {
            int y = __shfl_up_sync(0xffffu, s, off);
            if (t >= off) s += y;
        }
        ws[t] = s;
    }
    __syncthreads();
    int excl = x - v + (w ? ws[w - 1] : 0);
    if (i < N_NODES) g_rowptr[i] = excl;
    if (t == 511) g_blk[blockIdx.x] = excl + v;
}
__global__ void scan2_kernel(int nblk) {
    __shared__ int sh[128];
    const int t = threadIdx.x;
    sh[t] = (t < nblk) ? g_blk[t] : 0;
    __syncthreads();
    if (t == 0) {
        int run = 0;
        for (int i = 0; i < nblk; ++i) { int v = sh[i]; sh[i] = run; run += v; }
        g_rowptr[N_NODES] = run;
    }
    __syncthreads();
    if (t < nblk) g_blkoff[t] = sh[t];
}
__global__ void scan3_kernel() {
    int i = blockIdx.x * blockDim.x + threadIdx.x;
    if (i < N_NODES) {
        int r = g_rowptr[i] + g_blkoff[i >> 9];
        g_rowptr[i] = r;
        g_wptr[i]   = r;
    }
}
__global__ void scatter_kernel(const void* __restrict__ ei) {
    int e = blockIdx.x * blockDim.x + threadIdx.x;
    if (e < N_EDGES) {
        int s = edge_at(ei, e);
        int d = edge_at(ei, N_EDGES + e);
        g_csrc[atomicAdd(&g_wptr[d], 1)] = s;
    }
}

// ================= bf16 helpers =================
__device__ __forceinline__ unsigned bf2bits(__nv_bfloat162 v) {
    return *reinterpret_cast<unsigned*>(&v);
}
__device__ __forceinline__ uint2 round4(float4 v) {
    __nv_bfloat162 h01 = __float22bfloat162_rn(make_float2(v.x, v.y));
    __nv_bfloat162 h23 = __float22bfloat162_rn(make_float2(v.z, v.w));
    uint2 h;
    h.x = bf2bits(h01); h.y = bf2bits(h23);
    return h;
}

// fp32 [total elems] -> bf16 [padtotal], zero-fill padding. i indexes groups of 4.
__global__ void conv_bf16(const float* __restrict__ src, __nv_bfloat16* __restrict__ dst,
                          int total4, int padtotal4)
{
    int i = blockIdx.x * blockDim.x + threadIdx.x;
    if (i >= padtotal4) return;
    float4 v = (i < total4) ? ((const float4*)src)[i] : make_float4(0.f, 0.f, 0.f, 0.f);
    *(uint2*)(dst + (size_t)i * 4) = round4(v);
}

// ================= weight pre-pack =================
// src: [K,128] fp32 row-major -> tile (c64,w): [128 n][64 k] bf16 contiguous
__global__ void prepack_b(const float* __restrict__ s0, const float* __restrict__ s1,
                          const float* __restrict__ s2, const float* __restrict__ s3,
                          __nv_bfloat16* __restrict__ dst)
{
    const int c = blockIdx.x >> 2;
    const int w = blockIdx.x & 3;
    const float* src = (w == 0) ? s0 : (w == 1) ? s1 : (w == 2) ? s2 : s3;
    __nv_bfloat16* hi = dst + (size_t)(c * 4 + w) * 8192;
    for (int idx = threadIdx.x; idx < 2048; idx += blockDim.x) {
        const int n  = idx >> 4;
        const int k  = (idx & 15) * 4;
        const int kb = c * 64 + k;
        float4 v;
        v.x = src[(size_t)(kb + 0) * 128 + n];
        v.y = src[(size_t)(kb + 1) * 128 + n];
        v.z = src[(size_t)(kb + 2) * 128 + n];
        v.w = src[(size_t)(kb + 3) * 128 + n];
        *(uint2*)(hi + n * 64 + k) = round4(v);
    }
}
__global__ void pack_bias(const float* __restrict__ a, const float* __restrict__ b,
                          const float* __restrict__ c, const float* __restrict__ d,
                          float* __restrict__ out)
{
    int t = threadIdx.x;   // 512
    out[t] = (t < 128) ? a[t] : (t < 256) ? b[t - 128] : (t < 384) ? c[t - 256] : d[t - 384];
}

// ================= mma.sync / cp.async helpers =================
__device__ __forceinline__ void ldsm_x4(uint32_t& r0, uint32_t& r1, uint32_t& r2, uint32_t& r3,
                                        uint32_t addr) {
    asm volatile("ldmatrix.sync.aligned.m8n8.x4.shared.b16 {%0,%1,%2,%3}, [%4];"
                 : "=r"(r0), "=r"(r1), "=r"(r2), "=r"(r3) : "r"(addr));
}
__device__ __forceinline__ void mma_bf16(float* c, const uint32_t* a, uint32_t b0, uint32_t b1) {
    asm volatile("mma.sync.aligned.m16n8k16.row.col.f32.bf16.bf16.f32 "
                 "{%0,%1,%2,%3}, {%4,%5,%6,%7}, {%8,%9}, {%0,%1,%2,%3};"
                 : "+f"(c[0]), "+f"(c[1]), "+f"(c[2]), "+f"(c[3])
                 : "r"(a[0]), "r"(a[1]), "r"(a[2]), "r"(a[3]), "r"(b0), "r"(b1));
}
__device__ __forceinline__ uint32_t smem_u32(const void* p) {
    uint32_t a;
    asm("{ .reg .u64 t; cvta.to.shared.u64 t, %1; cvt.u32.u64 %0, t; }" : "=r"(a) : "l"(p));
    return a;
}
__device__ __forceinline__ void cp_async16(uint32_t daddr, const void* gptr) {
    asm volatile("cp.async.cg.shared.global [%0], [%1], 16;" :: "r"(daddr), "l"(gptr));
}
__device__ __forceinline__ void cp_commit() { asm volatile("cp.async.commit_group;"); }

// ================= tensor-core GEMM (bf16 x bf16, double-buffered cp.async) =================
// A pre-converted to bf16 in gmem (rounding identical to the previous inline path).
#define ROWE 72                    // smem row stride in bf16 (64 + 8 pad -> 144 B)
#define STAGE_BYTES 36864          // A tile 18432 + B tile 18432
#define SM_BOFF 18432
#define SM_GEMM_BYTES (2 * STAGE_BYTES)

__global__ __launch_bounds__(256, 2)
void gemm_mma(const __nv_bfloat16* __restrict__ Abf, int K, int M,
              const __nv_bfloat16* __restrict__ Bpre,
              const float* __restrict__ bias512,
              float* __restrict__ q, float* __restrict__ kv, float* __restrict__ skip)
{
    extern __shared__ __align__(16) char smem[];
    const uint32_t sbase = smem_u32(smem);
    const int tid = threadIdx.x, lane = tid & 31, wid = tid >> 5;
    const int wm = wid & 3, wn = wid >> 2;          // warp tile: 32 M x 64 N
    const int w = blockIdx.x;
    const int row0 = blockIdx.y * 128;
    const int nchunks = K >> 6;

    float acc[2][8][4];
    #pragma unroll
    for (int i = 0; i < 2; i++)
        #pragma unroll
        for (int j = 0; j < 8; j++)
            #pragma unroll
            for (int t = 0; t < 4; t++) acc[i][j][t] = 0.f;

    const int g = lane >> 3, r = lane & 7;
    const uint32_t a_rel = (uint32_t)(((wm * 32 + (g & 1) * 8 + r) * ROWE + (g >> 1) * 8) * 2);
    const uint32_t b_rel = (uint32_t)(((wn * 64 + (g & 1) * 8 + r) * ROWE + (g >> 1) * 8) * 2) + SM_BOFF;

    // per-thread fixed granule coords (u = tid + it*256; m/n = u>>3, f = u&7)
    // issue one chunk's A+B into stage (c&1)
    #define ISSUE_CHUNK(c)                                                          \
    {                                                                               \
        const uint32_t st = sbase + (((c) & 1) ? STAGE_BYTES : 0);                  \
        const __nv_bfloat16* bsrc = Bpre + (size_t)((c) * 4 + w) * 8192;            \
        const __nv_bfloat16* asrc = Abf + (size_t)row0 * K + (c) * 64;              \
        _Pragma("unroll")                                                           \
        for (int it = 0; it < 4; ++it) {                                            \
            int u = tid + it * 256;                                                 \
            int n = u >> 3, f = u & 7;                                              \
            cp_async16(st + SM_BOFF + n * (ROWE * 2) + f * 16, bsrc + (size_t)u * 8); \
        }                                                                           \
        _Pragma("unroll")                                                           \
        for (int it = 0; it < 4; ++it) {                                            \
            int u = tid + it * 256;                                                 \
            int m = u >> 3, f = u & 7;                                              \
            cp_async16(st + m * (ROWE * 2) + f * 16, asrc + (size_t)m * K + f * 8); \
        }                                                                           \
        cp_commit();                                                                \
    }

    ISSUE_CHUNK(0);

    for (int c = 0; c < nchunks; ++c) {
        if (c + 1 < nchunks) {
            ISSUE_CHUNK(c + 1);
            asm volatile("cp.async.wait_group 1;");
        } else {
            asm volatile("cp.async.wait_group 0;");
        }
        __syncthreads();

        const uint32_t st = sbase + ((c & 1) ? STAGE_BYTES : 0);
        const uint32_t a0 = st + a_rel;
        const uint32_t b0 = st + b_rel;
        #pragma unroll
        for (int ks = 0; ks < 4; ++ks) {
            uint32_t ah[2][4];
            #pragma unroll
            for (int mi = 0; mi < 2; ++mi) {
                uint32_t off = (uint32_t)(mi * 16 * ROWE + ks * 16) * 2;
                ldsm_x4(ah[mi][0], ah[mi][1], ah[mi][2], ah[mi][3], a0 + off);
            }
            #pragma unroll
            for (int n2 = 0; n2 < 4; ++n2) {
                uint32_t off = (uint32_t)(n2 * 16 * ROWE + ks * 16) * 2;
                uint32_t bh0, bh1, bh2, bh3;
                ldsm_x4(bh0, bh1, bh2, bh3, b0 + off);
                #pragma unroll
                for (int mi = 0; mi < 2; ++mi) {
                    mma_bf16(acc[mi][n2 * 2],     ah[mi], bh0, bh2);
                    mma_bf16(acc[mi][n2 * 2 + 1], ah[mi], bh1, bh3);
                }
            }
        }
        __syncthreads();
    }

    // ---- epilogue ----
    const int ldc  = (w == 1 || w == 2) ? 256 : 128;
    const int coff = (w == 2) ? 128 : 0;
    float* C = (w == 0) ? q : (w == 3) ? skip : kv;
    #pragma unroll
    for (int mi = 0; mi < 2; ++mi) {
        const int ra = row0 + wm * 32 + mi * 16 + (lane >> 2);
        #pragma unroll
        for (int ni = 0; ni < 8; ++ni) {
            const int col = wn * 64 + ni * 8 + (lane & 3) * 2;
            const float b0 = bias512[w * 128 + col];
            const float b1 = bias512[w * 128 + col + 1];
            if (ra < M) {
                float2 o = make_float2(acc[mi][ni][0] + b0, acc[mi][ni][1] + b1);
                *(float2*)(C + (size_t)ra * ldc + coff + col) = o;
            }
            if (ra + 8 < M) {
                float2 o = make_float2(acc[mi][ni][2] + b0, acc[mi][ni][3] + b1);
                *(float2*)(C + (size_t)(ra + 8) * ldc + coff + col) = o;
            }
        }
    }
}

// ================= fused edge attention (warp/node, float4 lanes, 2-edge ILP) =================
__global__ __launch_bounds__(256)
void attn_kernel(const float* __restrict__ q, const float* __restrict__ kv,
                 const float* __restrict__ skip, float* __restrict__ out)
{
    const int node = (blockIdx.x * blockDim.x + threadIdx.x) >> 5;
    const int lane = threadIdx.x & 31;
    if (node >= N_NODES) return;

    const float4 q4 = *(const float4*)(q + (size_t)node * D_H + lane * 4);
    const float scale = 0.08838834764831845f;   // 1/sqrt(128)

    const int beg = g_rowptr[node], end = g_rowptr[node + 1];
    float mA = -1e30f, dA = 0.f;
    float4 aA = make_float4(0.f, 0.f, 0.f, 0.f);
    float mB = -1e30f, dB = 0.f;
    float4 aB = make_float4(0.f, 0.f, 0.f, 0.f);

    int p = beg;
    for (; p + 1 < end; p += 2) {
        const int sA = g_csrc[p], sB = g_csrc[p + 1];
        const float* ka = kv + (size_t)sA * 256;
        const float* kb = kv + (size_t)sB * 256;
        const float4 k4a = *(const float4*)(ka + lane * 4);
        const float4 k4b = *(const float4*)(kb + lane * 4);
        float pa = q4.x * k4a.x + q4.y * k4a.y + q4.z * k4a.z + q4.w * k4a.w;
        float pb = q4.x * k4b.x + q4.y * k4b.y + q4.z * k4b.z + q4.w * k4b.w;
        #pragma unroll
        for (int off = 16; off; off >>= 1) {
            pa += __shfl_xor_sync(0xffffffffu, pa, off);
            pb += __shfl_xor_sync(0xffffffffu, pb, off);
        }
        const float sa = pa * scale, sb = pb * scale;
        const float nmA = fmaxf(mA, sa), nmB = fmaxf(mB, sb);
        const float cA = __expf(mA - nmA), cB = __expf(mB - nmB);
        const float wa = __expf(sa - nmA), wb = __expf(sb - nmB);
        dA = dA * cA + wa;  dB = dB * cB + wb;
        const float4 v4a = *(const float4*)(ka + 128 + lane * 4);
        const float4 v4b = *(const float4*)(kb + 128 + lane * 4);
        aA.x = aA.x * cA + wa * v4a.x;  aB.x = aB.x * cB + wb * v4b.x;
        aA.y = aA.y * cA + wa * v4a.y;  aB.y = aB.y * cB + wb * v4b.y;
        aA.z = aA.z * cA + wa * v4a.z;  aB.z = aB.z * cB + wb * v4b.z;
        aA.w = aA.w * cA + wa * v4a.w;  aB.w = aB.w * cB + wb * v4b.w;
        mA = nmA; mB = nmB;
    }
    if (p < end) {
        const int s = g_csrc[p];
        const float* kr = kv + (size_t)s * 256;
        const float4 k4 = *(const float4*)(kr + lane * 4);
        float pa = q4.x * k4.x + q4.y * k4.y + q4.z * k4.z + q4.w * k4.w;
        #pragma unroll
        for (int off = 16; off; off >>= 1) pa += __shfl_xor_sync(0xffffffffu, pa, off);
        const float sa = pa * scale;
        const float nmA = fmaxf(mA, sa);
        const float cA = __expf(mA - nmA), wa = __expf(sa - nmA);
        dA = dA * cA + wa;
        const float4 v4 = *(const float4*)(kr + 128 + lane * 4);
        aA.x = aA.x * cA + wa * v4.x;
        aA.y = aA.y * cA + wa * v4.y;
        aA.z = aA.z * cA + wa * v4.z;
        aA.w = aA.w * cA + wa * v4.w;
        mA = nmA;
    }
    const float m = fmaxf(mA, mB);
    const float cA = __expf(mA - m), cB = __expf(mB - m);
    const float den = dA * cA + dB * cB;
    const float inv = (den > 0.f) ? (1.f / den) : 0.f;

    const float4 sk = *(const float4*)(skip + (size_t)node * D_H + lane * 4);
    float4 o;
    o.x = fmaxf((aA.x * cA + aB.x * cB) * inv + sk.x, 0.f);
    o.y = fmaxf((aA.y * cA + aB.y * cB) * inv + sk.y, 0.f);
    o.z = fmaxf((aA.z * cA + aB.z * cB) * inv + sk.z, 0.f);
    o.w = fmaxf((aA.w * cA + aB.w * cB) * inv + sk.w, 0.f);
    *(float4*)(out + (size_t)node * D_H + lane * 4) = o;
}

// ================= gather + MLP head =================
__global__ __launch_bounds__(128)
void head_kernel(const float* __restrict__ h, const void* __restrict__ idxbuf,
                 const float* __restrict__ mw1, const float* __restrict__ mb1,
                 const float* __restrict__ mw2, const float* __restrict__ mb2,
                 const float* __restrict__ mw3, const float* __restrict__ mb3,
                 float* __restrict__ out)
{
    __shared__ float sh[D_H];
    __shared__ float sh2[D_H];
    __shared__ float sh3[64];
    __shared__ float wsum[4];
    const int g = blockIdx.x, t = threadIdx.x;

    const int node = g_is64 ? (int)((const long long*)idxbuf)[g]
                            : ((const int*)idxbuf)[g];
    sh[t] = h[(size_t)node * D_H + t];
    __syncthreads();

    float s = mb1[t];
    #pragma unroll 8
    for (int k = 0; k < D_H; k++) s = fmaf(sh[k], mw1[k * D_H + t], s);
    sh2[t] = fmaxf(s, 0.f);
    __syncthreads();

    if (t < 64) {
        float s2 = mb2[t];
        #pragma unroll 8
        for (int k = 0; k < D_H; k++) s2 = fmaf(sh2[k], mw2[k * 64 + t], s2);
        sh3[t] = fmaxf(s2, 0.f);
    }
    __syncthreads();

    float p = (t < 64) ? sh3[t] * mw3[t] : 0.f;
    #pragma unroll
    for (int off = 16; off; off >>= 1) p += __shfl_xor_sync(0xffffffffu, p, off);
    if ((t & 31) == 0) wsum[t >> 5] = p;
    __syncthreads();
    if (t == 0) {
        float tot = wsum[0] + wsum[1] + wsum[2] + wsum[3] + mb3[0];
        out[g] = 1.f / (1.f + __expf(-tot));
    }
}

// ================= launch =================
extern "C" void kernel_launch(void* const* d_in, const int* in_sizes, int n_in,
                              void* d_out, int out_size)
{
    const float* x   = (const float*)d_in[0];
    const void*  ei  = d_in[1];
    const void*  idx = d_in[2];
    const float* wq0 = (const float*)d_in[3];
    const float* wk0 = (const float*)d_in[4];
    const float* wv0 = (const float*)d_in[5];
    const float* ws0 = (const float*)d_in[6];
    const float* bq0 = (const float*)d_in[7];
    const float* bk0 = (const float*)d_in[8];
    const float* bv0 = (const float*)d_in[9];
    const float* bs0 = (const float*)d_in[10];
    const float* wq1 = (const float*)d_in[11];
    const float* wk1 = (const float*)d_in[12];
    const float* wv1 = (const float*)d_in[13];
    const float* ws1 = (const float*)d_in[14];
    const float* bq1 = (const float*)d_in[15];
    const float* bk1 = (const float*)d_in[16];
    const float* bv1 = (const float*)d_in[17];
    const float* bs1 = (const float*)d_in[18];
    const float* mw1 = (const float*)d_in[19];
    const float* mb1 = (const float*)d_in[20];
    const float* mw2 = (const float*)d_in[21];
    const float* mb2 = (const float*)d_in[22];
    const float* mw3 = (const float*)d_in[23];
    const float* mb3 = (const float*)d_in[24];
    float* out = (float*)d_out;

    float *qp, *kvp, *skp, *h0p, *h1p, *bias0, *bias1;
    __nv_bfloat16 *bp0, *bp1, *xbf, *h0bf;
    cudaGetSymbolAddress((void**)&qp,    g_q);
    cudaGetSymbolAddress((void**)&kvp,   g_kv);
    cudaGetSymbolAddress((void**)&skp,   g_skip);
    cudaGetSymbolAddress((void**)&h0p,   g_h0);
    cudaGetSymbolAddress((void**)&h1p,   g_h1);
    cudaGetSymbolAddress((void**)&bp0,   g_bpre0);
    cudaGetSymbolAddress((void**)&bp1,   g_bpre1);
    cudaGetSymbolAddress((void**)&xbf,   g_xbf);
    cudaGetSymbolAddress((void**)&h0bf,  g_h0bf);
    cudaGetSymbolAddress((void**)&bias0, g_bias0);
    cudaGetSymbolAddress((void**)&bias1, g_bias1);

    cudaFuncSetAttribute(gemm_mma, cudaFuncAttributeMaxDynamicSharedMemorySize, SM_GEMM_BYTES);

    // index dtype + CSR
    detect_idx_dtype<<<1, 1024>>>((const long long*)ei);
    zero_cnt_kernel<<<(N_NODES + 255) / 256, 256>>>();
    count_deg_kernel<<<(N_EDGES + 255) / 256, 256>>>(ei);
    const int nblk = (N_NODES + 511) / 512;   // 98
    scan1_kernel<<<nblk, 512>>>();
    scan2_kernel<<<1, 128>>>(nblk);
    scan3_kernel<<<(N_NODES + 255) / 256, 256>>>();
    scatter_kernel<<<(N_EDGES + 255) / 256, 256>>>(ei);

    // weight pre-pack + bias pack
    prepack_b<<<16 * 4, 256>>>(wq0, wk0, wv0, ws0, bp0);
    prepack_b<<<2 * 4, 256>>>(wq1, wk1, wv1, ws1, bp1);
    pack_bias<<<1, 512>>>(bq0, bk0, bv0, bs0, bias0);
    pack_bias<<<1, 512>>>(bq1, bk1, bv1, bs1, bias1);

    // pre-convert x -> bf16 (rounding identical to the previous inline path)
    {
        const int t4 = N_NODES * D_IN / 4, p4 = MPAD * D_IN / 4;
        conv_bf16<<<(p4 + 255) / 256, 256>>>(x, xbf, t4, p4);
    }

    const int gm = (N_NODES + 127) / 128;     // 391
    dim3 ggrid(4, gm);                        // w fast-varying -> A L2 reuse

    // layer 0: 1024 -> 128 (x4 weights)
    gemm_mma<<<ggrid, 256, SM_GEMM_BYTES>>>(xbf, D_IN, N_NODES, bp0, bias0, qp, kvp, skp);
    attn_kernel<<<(N_NODES * 32 + 255) / 256, 256>>>(qp, kvp, skp, h0p);

    // convert h0 -> bf16, then layer 1: 128 -> 128 (x4 weights)
    {
        const int t4 = N_NODES * D_H / 4, p4 = MPAD * D_H / 4;
        conv_bf16<<<(p4 + 255) / 256, 256>>>(h0p, h0bf, t4, p4);
    }
    gemm_mma<<<ggrid, 256, SM_GEMM_BYTES>>>(h0bf, D_H, N_NODES, bp1, bias1, qp, kvp, skp);
    attn_kernel<<<(N_NODES * 32 + 255) / 256, 256>>>(qp, kvp, skp, h1p);

    // head
    head_kernel<<<N_GRAPHS, 128>>>(h1p, idx, mw1, mb1, mw2, mb2, mw3, mb3, out);
}

// round 14
// speedup vs baseline: 1.2264x; 1.2264x over previous
#include <cuda_runtime.h>
#include <cuda_bf16.h>
#include <math.h>
#include <stdint.h>

#define N_NODES  50000
#define N_EDGES  600000
#define D_IN     1024
#define D_H      128
#define N_GRAPHS 1000

// ================= device scratch (static, no allocation) =================
__device__ int   g_is64;
__device__ int   g_cnt[N_NODES];
__device__ int   g_rowptr[N_NODES + 1];
__device__ int   g_wptr[N_NODES];
__device__ int   g_csrc[N_EDGES];
__device__ int   g_blk[128];
__device__ int   g_blkoff[128];

__device__ float g_q   [(size_t)N_NODES * D_H];
__device__ __align__(16) __nv_bfloat16 g_kvbf[(size_t)N_NODES * 2 * D_H];  // k [0,128), v [128,256)
__device__ float g_skip[(size_t)N_NODES * D_H];
__device__ float g_h0  [(size_t)N_NODES * D_H];
__device__ float g_h1  [(size_t)N_NODES * D_H];

// pre-packed bf16 weight tiles: [chunk64][w][128 n][64 k]
__device__ __align__(16) __nv_bfloat16 g_bpre0[16 * 4 * 8192];  // 1 MB
__device__ __align__(16) __nv_bfloat16 g_bpre1[2  * 4 * 8192];  // 128 KB
__device__ float g_bias0[512];
__device__ float g_bias1[512];

// ================= index dtype detection (int64 vs int32) =================
__global__ void detect_idx_dtype(const long long* __restrict__ p) {
    __shared__ int bad;
    if (threadIdx.x == 0) bad = 0;
    __syncthreads();
    long long v = p[threadIdx.x];
    if (v < 0 || v >= N_NODES) atomicOr(&bad, 1);
    __syncthreads();
    if (threadIdx.x == 0) g_is64 = (bad == 0) ? 1 : 0;
}
__device__ __forceinline__ int edge_at(const void* ei, int pos) {
    if (g_is64) return (int)((const long long*)ei)[pos];
    return ((const int*)ei)[pos];
}

// ================= CSR build =================
__global__ void zero_cnt_kernel() {
    int i = blockIdx.x * blockDim.x + threadIdx.x;
    if (i < N_NODES) g_cnt[i] = 0;
}
__global__ void count_deg_kernel(const void* __restrict__ ei) {
    int e = blockIdx.x * blockDim.x + threadIdx.x;
    if (e < N_EDGES) atomicAdd(&g_cnt[edge_at(ei, N_EDGES + e)], 1);
}
__global__ void scan1_kernel() {
    __shared__ int ws[16];
    const int t = threadIdx.x, lane = t & 31, w = t >> 5;
    const int i = blockIdx.x * 512 + t;
    int v = (i < N_NODES) ? g_cnt[i] : 0;
    int x = v;
    #pragma unroll
    for (int off = 1; off < 32; off <<= 1) {
        int y = __shfl_up_sync(0xffffffffu, x, off);
        if (lane >= off) x += y;
    }
    if (lane == 31) ws[w] = x;
    __syncthreads();
    if (t < 16) {
        int s = ws[t];
        #pragma unroll
        for (int off = 1; off < 16; off <<= 1) {
            int y = __shfl_up_sync(0xffffu, s, off);
            if (t >= off) s += y;
        }
        ws[t] = s;
    }
    __syncthreads();
    int excl = x - v + (w ? ws[w - 1] : 0);
    if (i < N_NODES) g_rowptr[i] = excl;
    if (t == 511) g_blk[blockIdx.x] = excl + v;
}
__global__ void scan2_kernel(int nblk) {
    __shared__ int sh[128];
    const int t = threadIdx.x;
    sh[t] = (t < nblk) ? g_blk[t] : 0;
    __syncthreads();
    if (t == 0) {
        int run = 0;
        for (int i = 0; i < nblk; ++i) { int v = sh[i]; sh[i] = run; run += v; }
        g_rowptr[N_NODES] = run;
    }
    __syncthreads();
    if (t < nblk) g_blkoff[t] = sh[t];
}
__global__ void scan3_kernel() {
    int i = blockIdx.x * blockDim.x + threadIdx.x;
    if (i < N_NODES) {
        int r = g_rowptr[i] + g_blkoff[i >> 9];
        g_rowptr[i] = r;
        g_wptr[i]   = r;
    }
}
__global__ void scatter_kernel(const void* __restrict__ ei) {
    int e = blockIdx.x * blockDim.x + threadIdx.x;
    if (e < N_EDGES) {
        int s = edge_at(ei, e);
        int d = edge_at(ei, N_EDGES + e);
        g_csrc[atomicAdd(&g_wptr[d], 1)] = s;
    }
}

// ================= bf16 helpers =================
__device__ __forceinline__ unsigned bf2bits(__nv_bfloat162 v) {
    return *reinterpret_cast<unsigned*>(&v);
}
__device__ __forceinline__ uint2 round4(float4 v) {
    __nv_bfloat162 h01 = __float22bfloat162_rn(make_float2(v.x, v.y));
    __nv_bfloat162 h23 = __float22bfloat162_rn(make_float2(v.z, v.w));
    uint2 h;
    h.x = bf2bits(h01); h.y = bf2bits(h23);
    return h;
}

// ================= weight pre-pack =================
// src: [K,128] fp32 row-major -> tile (c64,w): [128 n][64 k] bf16 contiguous
__global__ void prepack_b(const float* __restrict__ s0, const float* __restrict__ s1,
                          const float* __restrict__ s2, const float* __restrict__ s3,
                          __nv_bfloat16* __restrict__ dst)
{
    const int c = blockIdx.x >> 2;
    const int w = blockIdx.x & 3;
    const float* src = (w == 0) ? s0 : (w == 1) ? s1 : (w == 2) ? s2 : s3;
    __nv_bfloat16* hi = dst + (size_t)(c * 4 + w) * 8192;
    for (int idx = threadIdx.x; idx < 2048; idx += blockDim.x) {
        const int n  = idx >> 4;
        const int k  = (idx & 15) * 4;
        const int kb = c * 64 + k;
        float4 v;
        v.x = src[(size_t)(kb + 0) * 128 + n];
        v.y = src[(size_t)(kb + 1) * 128 + n];
        v.z = src[(size_t)(kb + 2) * 128 + n];
        v.w = src[(size_t)(kb + 3) * 128 + n];
        *(uint2*)(hi + n * 64 + k) = round4(v);
    }
}
__global__ void pack_bias(const float* __restrict__ a, const float* __restrict__ b,
                          const float* __restrict__ c, const float* __restrict__ d,
                          float* __restrict__ out)
{
    int t = threadIdx.x;   // 512
    out[t] = (t < 128) ? a[t] : (t < 256) ? b[t - 128] : (t < 384) ? c[t - 256] : d[t - 384];
}

// ================= mma.sync / cp.async helpers =================
__device__ __forceinline__ void ldsm_x4(uint32_t& r0, uint32_t& r1, uint32_t& r2, uint32_t& r3,
                                        uint32_t addr) {
    asm volatile("ldmatrix.sync.aligned.m8n8.x4.shared.b16 {%0,%1,%2,%3}, [%4];"
                 : "=r"(r0), "=r"(r1), "=r"(r2), "=r"(r3) : "r"(addr));
}
__device__ __forceinline__ void mma_bf16(float* c, const uint32_t* a, uint32_t b0, uint32_t b1) {
    asm volatile("mma.sync.aligned.m16n8k16.row.col.f32.bf16.bf16.f32 "
                 "{%0,%1,%2,%3}, {%4,%5,%6,%7}, {%8,%9}, {%0,%1,%2,%3};"
                 : "+f"(c[0]), "+f"(c[1]), "+f"(c[2]), "+f"(c[3])
                 : "r"(a[0]), "r"(a[1]), "r"(a[2]), "r"(a[3]), "r"(b0), "r"(b1));
}
__device__ __forceinline__ uint32_t smem_u32(const void* p) {
    uint32_t a;
    asm("{ .reg .u64 t; cvta.to.shared.u64 t, %1; cvt.u32.u64 %0, t; }" : "=r"(a) : "l"(p));
    return a;
}
__device__ __forceinline__ void cp_async16(uint32_t daddr, const void* gptr) {
    asm volatile("cp.async.cg.shared.global [%0], [%1], 16;" :: "r"(daddr), "l"(gptr));
}
__device__ __forceinline__ void cp_commit() { asm volatile("cp.async.commit_group;"); }
__device__ __forceinline__ void cp_wait_all() { asm volatile("cp.async.wait_group 0;"); }

// ================= tensor-core GEMM (mma.sync, plain bf16 x bf16) =================
// w=0 -> q (fp32), w=3 -> skip (fp32), w=1/2 -> kvbf (bf16, interleaved k|v)
#define ROWE 72                    // smem row stride in bf16 (64 + 8 pad -> 144 B)
#define SM_AH 0
#define SM_BH 18432
#define SM_GEMM_BYTES 36864

__global__ __launch_bounds__(256, 2)
void gemm_mma(const float* __restrict__ A, int K, int M,
              const __nv_bfloat16* __restrict__ Bpre,
              const float* __restrict__ bias512,
              float* __restrict__ q, __nv_bfloat16* __restrict__ kvbf,
              float* __restrict__ skip)
{
    extern __shared__ __align__(16) char smem[];
    const uint32_t sbase = smem_u32(smem);
    const int tid = threadIdx.x, lane = tid & 31, wid = tid >> 5;
    const int wm = wid & 3, wn = wid >> 2;          // warp tile: 32 M x 64 N
    const int w = blockIdx.x;
    const int row0 = blockIdx.y * 128;
    const int nchunks = K >> 6;

    float acc[2][8][4];
    #pragma unroll
    for (int i = 0; i < 2; i++)
        #pragma unroll
        for (int j = 0; j < 8; j++)
            #pragma unroll
            for (int t = 0; t < 4; t++) acc[i][j][t] = 0.f;

    const int g = lane >> 3, r = lane & 7;
    const uint32_t a_off0 = sbase + ((wm * 32 + (g & 1) * 8 + r) * ROWE + (g >> 1) * 8) * 2;
    const uint32_t b_off0 = sbase + ((wn * 64 + (g & 1) * 8 + r) * ROWE + (g >> 1) * 8) * 2;

    for (int c = 0; c < nchunks; ++c) {
        // ---- issue B copy (cp.async overlaps with A load path) ----
        {
            const __nv_bfloat16* src = Bpre + (size_t)(c * 4 + w) * 8192;
            #pragma unroll
            for (int it = 0; it < 4; ++it) {
                int u = tid + it * 256;          // 0..1023 granules of 16B
                int n = u >> 3, f = u & 7;
                cp_async16(sbase + SM_BH + n * (ROWE * 2) + f * 16,
                           src + (size_t)u * 8);
            }
            cp_commit();
        }
        // ---- fill A (128 m x 64 k), bf16 round ----
        const int kc = c * 64;
        #pragma unroll
        for (int it = 0; it < 8; ++it) {
            int idx = tid + it * 256;
            int m = idx >> 4, kg = idx & 15;
            int gr = row0 + m;
            float4 v = (gr < M) ? *(const float4*)(A + (size_t)gr * K + kc + kg * 4)
                                : make_float4(0.f, 0.f, 0.f, 0.f);
            *(uint2*)(smem + SM_AH + m * (ROWE * 2) + kg * 8) = round4(v);
        }
        cp_wait_all();
        __syncthreads();

        // ---- compute: acc += A*B ----
        #pragma unroll
        for (int ks = 0; ks < 4; ++ks) {
            uint32_t ah[2][4];
            #pragma unroll
            for (int mi = 0; mi < 2; ++mi) {
                uint32_t off = (uint32_t)(mi * 16 * ROWE + ks * 16) * 2;
                ldsm_x4(ah[mi][0], ah[mi][1], ah[mi][2], ah[mi][3], SM_AH + a_off0 + off);
            }
            #pragma unroll
            for (int n2 = 0; n2 < 4; ++n2) {
                uint32_t off = (uint32_t)(n2 * 16 * ROWE + ks * 16) * 2;
                uint32_t bh0, bh1, bh2, bh3;
                ldsm_x4(bh0, bh1, bh2, bh3, SM_BH + b_off0 + off);
                #pragma unroll
                for (int mi = 0; mi < 2; ++mi) {
                    mma_bf16(acc[mi][n2 * 2],     ah[mi], bh0, bh2);
                    mma_bf16(acc[mi][n2 * 2 + 1], ah[mi], bh1, bh3);
                }
            }
        }
        __syncthreads();
    }

    // ---- epilogue ----
    if (w == 0 || w == 3) {
        float* C = (w == 0) ? q : skip;
        #pragma unroll
        for (int mi = 0; mi < 2; ++mi) {
            const int ra = row0 + wm * 32 + mi * 16 + (lane >> 2);
            #pragma unroll
            for (int ni = 0; ni < 8; ++ni) {
                const int col = wn * 64 + ni * 8 + (lane & 3) * 2;
                const float b0 = bias512[w * 128 + col];
                const float b1 = bias512[w * 128 + col + 1];
                if (ra < M)
                    *(float2*)(C + (size_t)ra * 128 + col) =
                        make_float2(acc[mi][ni][0] + b0, acc[mi][ni][1] + b1);
                if (ra + 8 < M)
                    *(float2*)(C + (size_t)(ra + 8) * 128 + col) =
                        make_float2(acc[mi][ni][2] + b0, acc[mi][ni][3] + b1);
            }
        }
    } else {
        // k (w=1) / v (w=2) -> bf16 interleaved buffer [N,256]
        const int coff = (w == 2) ? 128 : 0;
        #pragma unroll
        for (int mi = 0; mi < 2; ++mi) {
            const int ra = row0 + wm * 32 + mi * 16 + (lane >> 2);
            #pragma unroll
            for (int ni = 0; ni < 8; ++ni) {
                const int col = wn * 64 + ni * 8 + (lane & 3) * 2;
                const float b0 = bias512[w * 128 + col];
                const float b1 = bias512[w * 128 + col + 1];
                if (ra < M) {
                    __nv_bfloat162 o = __float22bfloat162_rn(
                        make_float2(acc[mi][ni][0] + b0, acc[mi][ni][1] + b1));
                    *(uint32_t*)(kvbf + (size_t)ra * 256 + coff + col) = bf2bits(o);
                }
                if (ra + 8 < M) {
                    __nv_bfloat162 o = __float22bfloat162_rn(
                        make_float2(acc[mi][ni][2] + b0, acc[mi][ni][3] + b1));
                    *(uint32_t*)(kvbf + (size_t)(ra + 8) * 256 + coff + col) = bf2bits(o);
                }
            }
        }
    }
}

// ================= fused edge attention (warp/node, bf16 KV, 2-edge ILP) =================
__device__ __forceinline__ float4 ld_kv4(const __nv_bfloat16* p) {
    uint2 raw = *(const uint2*)p;
    __nv_bfloat162 b01 = *reinterpret_cast<__nv_bfloat162*>(&raw.x);
    __nv_bfloat162 b23 = *reinterpret_cast<__nv_bfloat162*>(&raw.y);
    float2 f01 = __bfloat1622float2(b01);
    float2 f23 = __bfloat1622float2(b23);
    return make_float4(f01.x, f01.y, f23.x, f23.y);
}

__global__ __launch_bounds__(256)
void attn_kernel(const float* __restrict__ q, const __nv_bfloat16* __restrict__ kv,
                 const float* __restrict__ skip, float* __restrict__ out)
{
    const int node = (blockIdx.x * blockDim.x + threadIdx.x) >> 5;
    const int lane = threadIdx.x & 31;
    if (node >= N_NODES) return;

    const float4 q4 = *(const float4*)(q + (size_t)node * D_H + lane * 4);
    const float scale = 0.08838834764831845f;   // 1/sqrt(128)

    const int beg = g_rowptr[node], end = g_rowptr[node + 1];
    float mA = -1e30f, dA = 0.f;
    float4 aA = make_float4(0.f, 0.f, 0.f, 0.f);
    float mB = -1e30f, dB = 0.f;
    float4 aB = make_float4(0.f, 0.f, 0.f, 0.f);

    int p = beg;
    for (; p + 1 < end; p += 2) {
        const int sA = g_csrc[p], sB = g_csrc[p + 1];
        const __nv_bfloat16* ka = kv + (size_t)sA * 256;
        const __nv_bfloat16* kb = kv + (size_t)sB * 256;
        const float4 k4a = ld_kv4(ka + lane * 4);
        const float4 k4b = ld_kv4(kb + lane * 4);
        float pa = q4.x * k4a.x + q4.y * k4a.y + q4.z * k4a.z + q4.w * k4a.w;
        float pb = q4.x * k4b.x + q4.y * k4b.y + q4.z * k4b.z + q4.w * k4b.w;
        #pragma unroll
        for (int off = 16; off; off >>= 1) {
            pa += __shfl_xor_sync(0xffffffffu, pa, off);
            pb += __shfl_xor_sync(0xffffffffu, pb, off);
        }
        const float sa = pa * scale, sb = pb * scale;
        const float nmA = fmaxf(mA, sa), nmB = fmaxf(mB, sb);
        const float cA = __expf(mA - nmA), cB = __expf(mB - nmB);
        const float wa = __expf(sa - nmA), wb = __expf(sb - nmB);
        dA = dA * cA + wa;  dB = dB * cB + wb;
        const float4 v4a = ld_kv4(ka + 128 + lane * 4);
        const float4 v4b = ld_kv4(kb + 128 + lane * 4);
        aA.x = aA.x * cA + wa * v4a.x;  aB.x = aB.x * cB + wb * v4b.x;
        aA.y = aA.y * cA + wa * v4a.y;  aB.y = aB.y * cB + wb * v4b.y;
        aA.z = aA.z * cA + wa * v4a.z;  aB.z = aB.z * cB + wb * v4b.z;
        aA.w = aA.w * cA + wa * v4a.w;  aB.w = aB.w * cB + wb * v4b.w;
        mA = nmA; mB = nmB;
    }
    if (p < end) {
        const int s = g_csrc[p];
        const __nv_bfloat16* kr = kv + (size_t)s * 256;
        const float4 k4 = ld_kv4(kr + lane * 4);
        float pa = q4.x * k4.x + q4.y * k4.y + q4.z * k4.z + q4.w * k4.w;
        #pragma unroll
        for (int off = 16; off; off >>= 1) pa += __shfl_xor_sync(0xffffffffu, pa, off);
        const float sa = pa * scale;
        const float nmA = fmaxf(mA, sa);
        const float cA = __expf(mA - nmA), wa = __expf(sa - nmA);
        dA = dA * cA + wa;
        const float4 v4 = ld_kv4(kr + 128 + lane * 4);
        aA.x = aA.x * cA + wa * v4.x;
        aA.y = aA.y * cA + wa * v4.y;
        aA.z = aA.z * cA + wa * v4.z;
        aA.w = aA.w * cA + wa * v4.w;
        mA = nmA;
    }
    const float m = fmaxf(mA, mB);
    const float cA = __expf(mA - m), cB = __expf(mB - m);
    const float den = dA * cA + dB * cB;
    const float inv = (den > 0.f) ? (1.f / den) : 0.f;

    const float4 sk = *(const float4*)(skip + (size_t)node * D_H + lane * 4);
    float4 o;
    o.x = fmaxf((aA.x * cA + aB.x * cB) * inv + sk.x, 0.f);
    o.y = fmaxf((aA.y * cA + aB.y * cB) * inv + sk.y, 0.f);
    o.z = fmaxf((aA.z * cA + aB.z * cB) * inv + sk.z, 0.f);
    o.w = fmaxf((aA.w * cA + aB.w * cB) * inv + sk.w, 0.f);
    *(float4*)(out + (size_t)node * D_H + lane * 4) = o;
}

// ================= gather + MLP head =================
__global__ __launch_bounds__(128)
void head_kernel(const float* __restrict__ h, const void* __restrict__ idxbuf,
                 const float* __restrict__ mw1, const float* __restrict__ mb1,
                 const float* __restrict__ mw2, const float* __restrict__ mb2,
                 const float* __restrict__ mw3, const float* __restrict__ mb3,
                 float* __restrict__ out)
{
    __shared__ float sh[D_H];
    __shared__ float sh2[D_H];
    __shared__ float sh3[64];
    __shared__ float wsum[4];
    const int g = blockIdx.x, t = threadIdx.x;

    const int node = g_is64 ? (int)((const long long*)idxbuf)[g]
                            : ((const int*)idxbuf)[g];
    sh[t] = h[(size_t)node * D_H + t];
    __syncthreads();

    float s = mb1[t];
    #pragma unroll 8
    for (int k = 0; k < D_H; k++) s = fmaf(sh[k], mw1[k * D_H + t], s);
    sh2[t] = fmaxf(s, 0.f);
    __syncthreads();

    if (t < 64) {
        float s2 = mb2[t];
        #pragma unroll 8
        for (int k = 0; k < D_H; k++) s2 = fmaf(sh2[k], mw2[k * 64 + t], s2);
        sh3[t] = fmaxf(s2, 0.f);
    }
    __syncthreads();

    float p = (t < 64) ? sh3[t] * mw3[t] : 0.f;
    #pragma unroll
    for (int off = 16; off; off >>= 1) p += __shfl_xor_sync(0xffffffffu, p, off);
    if ((t & 31) == 0) wsum[t >> 5] = p;
    __syncthreads();
    if (t == 0) {
        float tot = wsum[0] + wsum[1] + wsum[2] + wsum[3] + mb3[0];
        out[g] = 1.f / (1.f + __expf(-tot));
    }
}

// ================= launch =================
extern "C" void kernel_launch(void* const* d_in, const int* in_sizes, int n_in,
                              void* d_out, int out_size)
{
    const float* x   = (const float*)d_in[0];
    const void*  ei  = d_in[1];
    const void*  idx = d_in[2];
    const float* wq0 = (const float*)d_in[3];
    const float* wk0 = (const float*)d_in[4];
    const float* wv0 = (const float*)d_in[5];
    const float* ws0 = (const float*)d_in[6];
    const float* bq0 = (const float*)d_in[7];
    const float* bk0 = (const float*)d_in[8];
    const float* bv0 = (const float*)d_in[9];
    const float* bs0 = (const float*)d_in[10];
    const float* wq1 = (const float*)d_in[11];
    const float* wk1 = (const float*)d_in[12];
    const float* wv1 = (const float*)d_in[13];
    const float* ws1 = (const float*)d_in[14];
    const float* bq1 = (const float*)d_in[15];
    const float* bk1 = (const float*)d_in[16];
    const float* bv1 = (const float*)d_in[17];
    const float* bs1 = (const float*)d_in[18];
    const float* mw1 = (const float*)d_in[19];
    const float* mb1 = (const float*)d_in[20];
    const float* mw2 = (const float*)d_in[21];
    const float* mb2 = (const float*)d_in[22];
    const float* mw3 = (const float*)d_in[23];
    const float* mb3 = (const float*)d_in[24];
    float* out = (float*)d_out;

    float *qp, *skp, *h0p, *h1p, *bias0, *bias1;
    __nv_bfloat16 *bp0, *bp1, *kvp;
    cudaGetSymbolAddress((void**)&qp,    g_q);
    cudaGetSymbolAddress((void**)&kvp,   g_kvbf);
    cudaGetSymbolAddress((void**)&skp,   g_skip);
    cudaGetSymbolAddress((void**)&h0p,   g_h0);
    cudaGetSymbolAddress((void**)&h1p,   g_h1);
    cudaGetSymbolAddress((void**)&bp0,   g_bpre0);
    cudaGetSymbolAddress((void**)&bp1,   g_bpre1);
    cudaGetSymbolAddress((void**)&bias0, g_bias0);
    cudaGetSymbolAddress((void**)&bias1, g_bias1);

    cudaFuncSetAttribute(gemm_mma, cudaFuncAttributeMaxDynamicSharedMemorySize, SM_GEMM_BYTES);

    // index dtype + CSR
    detect_idx_dtype<<<1, 1024>>>((const long long*)ei);
    zero_cnt_kernel<<<(N_NODES + 255) / 256, 256>>>();
    count_deg_kernel<<<(N_EDGES + 255) / 256, 256>>>(ei);
    const int nblk = (N_NODES + 511) / 512;   // 98
    scan1_kernel<<<nblk, 512>>>();
    scan2_kernel<<<1, 128>>>(nblk);
    scan3_kernel<<<(N_NODES + 255) / 256, 256>>>();
    scatter_kernel<<<(N_EDGES + 255) / 256, 256>>>(ei);

    // weight pre-pack + bias pack
    prepack_b<<<16 * 4, 256>>>(wq0, wk0, wv0, ws0, bp0);
    prepack_b<<<2 * 4, 256>>>(wq1, wk1, wv1, ws1, bp1);
    pack_bias<<<1, 512>>>(bq0, bk0, bv0, bs0, bias0);
    pack_bias<<<1, 512>>>(bq1, bk1, bv1, bs1, bias1);

    const int gm = (N_NODES + 127) / 128;     // 391
    dim3 ggrid(4, gm);                        // w fast-varying -> A L2 reuse

    // layer 0: 1024 -> 128 (x4 weights)
    gemm_mma<<<ggrid, 256, SM_GEMM_BYTES>>>(x, D_IN, N_NODES, bp0, bias0, qp, kvp, skp);
    attn_kernel<<<(N_NODES * 32 + 255) / 256, 256>>>(qp, kvp, skp, h0p);

    // layer 1: 128 -> 128 (x4 weights)
    gemm_mma<<<ggrid, 256, SM_GEMM_BYTES>>>(h0p, D_H, N_NODES, bp1, bias1, qp, kvp, skp);
    attn_kernel<<<(N_NODES * 32 + 255) / 256, 256>>>(qp, kvp, skp, h1p);

    // head
    head_kernel<<<N_GRAPHS, 128>>>(h1p, idx, mw1, mb1, mw2, mb2, mw3, mb3, out);
}